// round 1
// baseline (speedup 1.0000x reference)
#include <cuda_runtime.h>
#include <cstdint>

typedef unsigned int u32;
typedef unsigned long long u64;

#define NB 32
#define NA 49056
#define NFG 7
#define TOPK 200
#define NM (NFG*TOPK)     // 1400
#define NMP 2048          // padded pow2 for bitonic
#define NW ((NM+31)/32)   // 44 bitmap words
#define DETS 200
#define NMSTHR 0.45f

// ---------------- scratch (device globals; no allocations allowed) ----------
__device__ float g_boxes[(size_t)NB*NA*4];          // clipped decoded boxes
__device__ float g_fg[(size_t)NB*NFG*NA];           // fg scores, class-major
__device__ float g_cand_score[NB*NFG*TOPK];
__device__ int   g_cand_anchor[NB*NFG*TOPK];

// ---------------- K1: softmax + decode -------------------------------------
__global__ void k1_softmax_decode(const float* __restrict__ logits,
                                  const float* __restrict__ deltas,
                                  const float* __restrict__ dbox)
{
    int idx = blockIdx.x*blockDim.x + threadIdx.x;
    if (idx >= NB*NA) return;
    int b = idx / NA;
    int a = idx - b*NA;

    float4 l0 = ((const float4*)logits)[idx*2+0];
    float4 l1 = ((const float4*)logits)[idx*2+1];
    float e[8] = {l0.x,l0.y,l0.z,l0.w,l1.x,l1.y,l1.z,l1.w};
    float mx = e[0];
#pragma unroll
    for (int i=1;i<8;i++) mx = fmaxf(mx,e[i]);
    float s = 0.f;
#pragma unroll
    for (int i=0;i<8;i++){ e[i] = expf(e[i]-mx); s += e[i]; }
#pragma unroll
    for (int c=0;c<7;c++)
        g_fg[((size_t)b*NFG + c)*NA + a] = e[c+1]/s;

    float4 d  = ((const float4*)deltas)[idx];
    float4 db = ((const float4*)dbox)[a];
    float w  = db.z - db.x, h = db.w - db.y;
    float cx = db.x + 0.5f*w, cy = db.y + 0.5f*h;
    float pcx = d.x/10.0f*w + cx;
    float pcy = d.y/10.0f*h + cy;
    float pw  = expf(d.z/5.0f)*w;
    float ph  = expf(d.w/5.0f)*h;
    float4 o;
    o.x = fminf(fmaxf(pcx - 0.5f*pw, 0.f), 1.f);
    o.y = fminf(fmaxf(pcy - 0.5f*ph, 0.f), 1.f);
    o.z = fminf(fmaxf(pcx + 0.5f*pw, 0.f), 1.f);
    o.w = fminf(fmaxf(pcy + 0.5f*ph, 0.f), 1.f);
    ((float4*)g_boxes)[idx] = o;
}

// ---------------- K2: exact per-(b,c) top-200 via bit-pattern binary search -
#define K2T 512
#define K2V 96         // ceil(49056/512)
#define EQN 1024

__global__ __launch_bounds__(K2T) void k2_topk()
{
    int bc = blockIdx.x;              // b*7 + c
    const float* sc = g_fg + (size_t)bc*NA;
    int tid = threadIdx.x;

    u32 v[K2V];
#pragma unroll
    for (int k=0;k<K2V;k++){
        int a = tid + k*K2T;
        v[k] = (a < NA) ? __float_as_uint(sc[a]) : 0u;  // scores > 0 => bits >= 1
    }

    __shared__ u32 shw[K2T/32];
    __shared__ u32 shtot;

    // find P = max{v : count(bits >= v) >= 200}; scores in (0,1]
    u32 lo = 1u, hi = 0x3F800000u;
    while (lo < hi){
        u32 mid = lo + ((hi - lo + 1) >> 1);
        u32 c = 0;
#pragma unroll
        for (int k=0;k<K2V;k++) c += (v[k] >= mid) ? 1u : 0u;
        c = __reduce_add_sync(0xffffffffu, c);
        if ((tid&31)==0) shw[tid>>5] = c;
        __syncthreads();
        if (tid==0){ u32 t=0; for (int i=0;i<K2T/32;i++) t += shw[i]; shtot = t; }
        __syncthreads();
        u32 total = shtot;
        if (total >= TOPK) lo = mid; else hi = mid - 1;
        __syncthreads();
    }
    u32 P = lo;

    // count strictly greater
    {
        u32 c = 0;
#pragma unroll
        for (int k=0;k<K2V;k++) c += (v[k] > P) ? 1u : 0u;
        c = __reduce_add_sync(0xffffffffu, c);
        if ((tid&31)==0) shw[tid>>5] = c;
        __syncthreads();
        if (tid==0){ u32 t=0; for (int i=0;i<K2T/32;i++) t += shw[i]; shtot = t; }
        __syncthreads();
    }
    int cg = (int)shtot;        // < 200
    int krem = TOPK - cg;       // >= 1, taken from ==P with smallest anchors

    __shared__ int shpos, shec;
    __shared__ u32 sheq[EQN];
    if (tid==0){ shpos = 0; shec = 0; }
    __syncthreads();

    float* outS = g_cand_score  + bc*TOPK;
    int*   outA = g_cand_anchor + bc*TOPK;
#pragma unroll
    for (int k=0;k<K2V;k++){
        int a = tid + k*K2T;
        if (a < NA){
            if (v[k] > P){
                int p = atomicAdd(&shpos, 1);
                outS[p] = __uint_as_float(v[k]);
                outA[p] = a;
            } else if (v[k] == P){
                int p = atomicAdd(&shec, 1);
                if (p < EQN) sheq[p] = (u32)a;
            }
        }
    }
    __syncthreads();
    int ec = min(shec, EQN);
    for (int i = tid; i < EQN; i += K2T) if (i >= ec) sheq[i] = 0xFFFFFFFFu;
    __syncthreads();
    // bitonic ascending on anchors so ties pick smallest indices (lax.top_k rule)
    for (int kk=2; kk<=EQN; kk<<=1){
        for (int j=kk>>1; j>0; j>>=1){
            for (int i=tid; i<EQN; i+=K2T){
                int ix = i ^ j;
                if (ix > i){
                    u32 a0 = sheq[i], a1 = sheq[ix];
                    bool up = ((i & kk) == 0);
                    if ((a0 > a1) == up){ sheq[i]=a1; sheq[ix]=a0; }
                }
            }
            __syncthreads();
        }
    }
    if (tid < krem){
        outS[cg + tid] = __uint_as_float(P);
        outA[cg + tid] = (int)sheq[tid];
    }
}

// ---------------- K3: per-batch sort + greedy NMS + output ------------------
// dynamic smem layout (arrays overlap the key buffer; barrier separates phases)
#define K3_DYN ((size_t)(8*NM*4 > NMP*8 ? 8*NM*4 : NMP*8))   // 44800 bytes

__global__ __launch_bounds__(1024) void k3_sort_nms(float* __restrict__ out)
{
    extern __shared__ unsigned char dyn[];
    u64*   keys   = (u64*)dyn;                 // [NMP] during sort phase
    float* sx0    = (float*)dyn;               // arrays reuse same space after
    float* sy0    = sx0 + NM;
    float* sx1    = sy0 + NM;
    float* sy1    = sx1 + NM;
    float* sarea  = sy1 + NM;
    float* sscore = sarea + NM;
    int*   sanchor= (int*)(sscore + NM);
    int*   slabel = sanchor + NM;

    __shared__ int sh_valid, sh_cur, sh_kept;
    __shared__ u32 keep_words[NW];
    __shared__ int keptList[DETS];

    int b = blockIdx.x;
    int tid = threadIdx.x;

    // build sort keys: score desc, class asc, anchor asc (matches ref ordering)
    for (int t = tid; t < NMP; t += blockDim.x){
        u64 nk = ~0ull;                        // pads/invalid sort to the end
        if (t < NM){
            int c    = t / TOPK;
            int slot = t - c*TOPK;
            float s = g_cand_score[(b*NFG + c)*TOPK + slot];
            int   a = g_cand_anchor[(b*NFG + c)*TOPK + slot];
            if (s > 0.01f){                    // LOW_SCORE filter
                u32 hi = __float_as_uint(s);
                u32 lo = ((u32)(7 - c) << 20) | (0xFFFFFu - (u32)a);
                nk = ~(((u64)hi << 32) | (u64)lo);   // sort ascending on ~key
            }
        }
        keys[t] = nk;
    }
    if (tid==0) sh_valid = 0;
    __syncthreads();

    // bitonic sort ascending on nk  => score descending
    for (int kk=2; kk<=NMP; kk<<=1){
        for (int j=kk>>1; j>0; j>>=1){
            for (int i=tid; i<NMP; i+=blockDim.x){
                int ix = i ^ j;
                if (ix > i){
                    u64 a0 = keys[i], a1 = keys[ix];
                    bool up = ((i & kk) == 0);
                    if ((a0 > a1) == up){ keys[i]=a1; keys[ix]=a0; }
                }
            }
            __syncthreads();
        }
    }

    // pull keys into regs, then overwrite smem with SoA candidate data
    u64 myk[2] = {~0ull, ~0ull};
    int myi[2] = {-1, -1};
    {
        int n = 0;
        for (int i = tid; i < NM; i += blockDim.x){ myk[n] = keys[i]; myi[n] = i; n++; }
    }
    __syncthreads();   // keys no longer needed; arrays may reuse the space

#pragma unroll
    for (int q=0; q<2; q++){
        int i = myi[q];
        if (i >= 0){
            u64 kk = ~myk[q];
            if (kk != 0ull){
                atomicMax(&sh_valid, i+1);
                u32 hi = (u32)(kk >> 32);
                u32 lo = (u32)kk;
                float s   = __uint_as_float(hi);
                int c     = 7 - (int)((lo >> 20) & 7u);
                int a     = (int)(0xFFFFFu - (lo & 0xFFFFFu));
                int label = c + 1;
                float4 bb = ((const float4*)g_boxes)[(size_t)b*NA + a];
                float off = 4.0f * (float)label;        // class offset, as ref
                float x0 = bb.x + off, y0 = bb.y + off;
                float x1 = bb.z + off, y1 = bb.w + off;
                sx0[i]=x0; sy0[i]=y0; sx1[i]=x1; sy1[i]=y1;
                sarea[i] = (x1-x0)*(y1-y0);             // area on rounded offsets (ref-exact)
                sscore[i] = s;
                sanchor[i] = a;
                slabel[i] = label;
            }
        }
    }
    __syncthreads();

    int valid = sh_valid;
    for (int w = tid; w < NW; w += blockDim.x){
        int full = valid - w*32;
        keep_words[w] = (full >= 32) ? 0xFFFFFFFFu
                      : (full <= 0 ? 0u : ((1u << full) - 1u));
    }
    if (tid==0){ sh_kept = 0; sh_cur = (valid > 0) ? 0 : -1; }
    __syncthreads();

    // greedy NMS with bitmap skip + early exit at 200 keeps
    while (sh_cur >= 0){
        int cur = sh_cur;
        int keptSoFar = sh_kept;
        if (tid == 0) keptList[keptSoFar] = cur;
        if (keptSoFar < DETS - 1){
            float x0 = sx0[cur], y0 = sy0[cur], x1 = sx1[cur], y1 = sy1[cur];
            float ar = sarea[cur];
            for (int j = cur + 1 + tid; j < valid; j += blockDim.x){
                u32 wv = keep_words[j >> 5];
                if ((wv >> (j & 31)) & 1u){
                    float xl = fmaxf(x0, sx0[j]);
                    float yt = fmaxf(y0, sy0[j]);
                    float xr = fminf(x1, sx1[j]);
                    float yb = fminf(y1, sy1[j]);
                    float iw = fmaxf(xr - xl, 0.f);
                    float ih = fmaxf(yb - yt, 0.f);
                    float inter = iw * ih;
                    float iou = inter / (ar + sarea[j] - inter);
                    if (iou > NMSTHR) atomicAnd(&keep_words[j >> 5], ~(1u << (j & 31)));
                }
            }
        }
        __syncthreads();
        if (tid == 0){
            int nk2 = keptSoFar + 1;
            sh_kept = nk2;
            if (nk2 >= DETS) sh_cur = -1;
            else {
                int nxt = -1;
                int ww = (cur + 1) >> 5;
                u32 word = (ww < NW) ? (keep_words[ww] & (0xFFFFFFFFu << ((cur + 1) & 31))) : 0u;
                while (true){
                    if (word){ nxt = (ww << 5) + __ffs((int)word) - 1; break; }
                    ww++;
                    if (ww >= NW) break;
                    word = keep_words[ww];
                }
                if (nxt >= valid) nxt = -1;
                sh_cur = nxt;
            }
        }
        __syncthreads();
    }

    // write output: [boxes | scores | labels], zero-filled past kept
    int kept = sh_kept;
    for (int d = tid; d < DETS; d += blockDim.x){
        float b0=0,b1=0,b2=0,b3=0,sv=0; int lab=0;
        if (d < kept){
            int i = keptList[d];
            int a = sanchor[i];
            float4 bb = ((const float4*)g_boxes)[(size_t)b*NA + a];
            b0=bb.x; b1=bb.y; b2=bb.z; b3=bb.w;
            sv = sscore[i]; lab = slabel[i];
        }
        int base = b*DETS + d;
        out[base*4+0]=b0; out[base*4+1]=b1; out[base*4+2]=b2; out[base*4+3]=b3;
        out[NB*DETS*4 + base] = sv;
        out[NB*DETS*5 + base] = (float)lab;
    }
}

// ---------------- launch ----------------------------------------------------
extern "C" void kernel_launch(void* const* d_in, const int* in_sizes, int n_in,
                              void* d_out, int out_size)
{
    const float* logits = (const float*)d_in[0];
    const float* deltas = (const float*)d_in[1];
    const float* dbox   = (const float*)d_in[2];
    float* out = (float*)d_out;

    int total = NB*NA;
    k1_softmax_decode<<<(total + 255)/256, 256>>>(logits, deltas, dbox);
    k2_topk<<<NB*NFG, K2T>>>();
    k3_sort_nms<<<NB, 1024, (int)K3_DYN>>>(out);
}

// round 2
// speedup vs baseline: 2.0736x; 2.0736x over previous
#include <cuda_runtime.h>
#include <cstdint>

typedef unsigned int u32;
typedef unsigned long long u64;

#define NB 32
#define NA 49056
#define NFG 7
#define TOPK 200
#define DETS 200
#define NMSTHR 0.45f
#define LOWSC 0.01f

#define K2T 512
#define NCH 96            // 96*512 = 49152 padded slots
#define NPAD 49152
#define N4 (NA/4)         // 12264 uint4 loads

// ---------------- scratch ----------------------------------------------------
__device__ float g_fg[(size_t)NB*NFG*NA];     // fg scores, class-major
__device__ float g_ks[NB*NFG*TOPK];           // kept scores (sorted desc)
__device__ int   g_ka[NB*NFG*TOPK];           // kept anchors
__device__ float4 g_kb[NB*NFG*TOPK];          // kept clipped boxes (unoffset)
__device__ int   g_kc[NB*NFG];                // kept counts

// ---------------- K1: softmax only ------------------------------------------
__global__ void k1_softmax(const float* __restrict__ logits)
{
    int idx = blockIdx.x*blockDim.x + threadIdx.x;
    if (idx >= NB*NA) return;
    int b = idx / NA;
    int a = idx - b*NA;

    float4 l0 = ((const float4*)logits)[idx*2+0];
    float4 l1 = ((const float4*)logits)[idx*2+1];
    float e[8] = {l0.x,l0.y,l0.z,l0.w,l1.x,l1.y,l1.z,l1.w};
    float mx = e[0];
#pragma unroll
    for (int i=1;i<8;i++) mx = fmaxf(mx,e[i]);
    float s = 0.f;
#pragma unroll
    for (int i=0;i<8;i++){ e[i] = expf(e[i]-mx); s += e[i]; }
#pragma unroll
    for (int c=0;c<7;c++)
        g_fg[((size_t)b*NFG + c)*NA + a] = e[c+1]/s;
}

// ---------------- K2: per-(b,c) top-200 + sort + class NMS -------------------
__global__ __launch_bounds__(K2T) void k2_select_nms(const float* __restrict__ deltas,
                                                     const float* __restrict__ dboxg)
{
    extern __shared__ u32 sv[];               // [NPAD] score bits

    __shared__ u32 shw[16];
    __shared__ u32 shtot;
    __shared__ int sh_pos, sh_ec, sh_pos2;
    __shared__ u32 cs[TOPK];                  // selected score bits
    __shared__ int ca[TOPK];                  // selected anchors
    __shared__ u32 eqA[256];
    __shared__ u64 skeys[256];
    __shared__ float4 rbox[TOPK];             // raw clipped boxes
    __shared__ float sx0[TOPK], sy0[TOPK], sx1[TOPK], sy1[TOPK], sar[TOPK];
    __shared__ u32 M[TOPK*7];
    __shared__ u32 skeep[7];
    __shared__ int warpcnt[8], warpbase[8], sh_tot;

    int bc = blockIdx.x;
    int b  = bc / NFG;
    int c  = bc - b*NFG;
    int tid = threadIdx.x;

    // ---- load class slice to smem (vectorized) ----
    {
        const uint4* src = (const uint4*)(reinterpret_cast<const u32*>(g_fg) + (size_t)bc*NA);
        uint4* dst = (uint4*)sv;
#pragma unroll
        for (int k=0;k<24;k++){
            int i4 = tid + (k<<9);
            if (i4 < N4) dst[i4] = src[i4];
        }
        for (int i = tid; i < NPAD-NA; i += K2T) sv[NA+i] = 0u;
    }
    __syncthreads();

    // ---- block count(>= piv) helper ----
    auto bcount = [&](u32 piv)->int{
        u32 cc = 0;
#pragma unroll
        for (int k=0;k<NCH;k++) cc += (sv[tid + (k<<9)] >= piv) ? 1u : 0u;
        cc = __reduce_add_sync(0xffffffffu, cc);
        __syncthreads();
        if ((tid&31)==0) shw[tid>>5] = cc;
        __syncthreads();
        if (tid==0){ u32 t=0; for (int i=0;i<16;i++) t += shw[i]; shtot = t; }
        __syncthreads();
        return (int)shtot;
    };

    // ---- threshold search (interpolation + bisection, early-exit at ==200) ----
    u32 lo = 1u, hi = 0x3F800001u;
    int clo = NA, chi = 0;
    u32 selT = 0; bool found = false;
    for (int it=0; it<70 && hi-lo>1u; ++it){
        u32 mid;
        if (it & 1){
            mid = lo + ((hi - lo) >> 1);
        } else {
            float fr = (float)(clo - TOPK) / (float)((clo - chi) > 0 ? (clo - chi) : 1);
            if (fr < 0.f) fr = 0.f; if (fr > 1.f) fr = 1.f;
            mid = lo + (u32)((float)(hi - lo) * fr);
            if (mid <= lo) mid = lo + 1;
            if (mid >= hi) mid = hi - 1;
        }
        int cm = bcount(mid);
        if (cm == TOPK){ selT = mid; found = true; break; }
        if (cm > TOPK){ lo = mid; clo = cm; }
        else          { hi = mid; chi = cm; }
    }

    // ---- emission of exactly 200 candidates ----
    if (tid==0){ sh_pos = 0; sh_ec = 0; sh_pos2 = 0; }
    __syncthreads();

    if (found){
#pragma unroll
        for (int k=0;k<NCH;k++){
            int a = tid + (k<<9);
            u32 v = sv[a];
            if (v >= selT){
                int p = atomicAdd(&sh_pos, 1);
                cs[p] = v; ca[p] = a;
            }
        }
        __syncthreads();
    } else {
        u32 P = lo;
        int cg = chi;                    // count strictly greater
        int krem = TOPK - cg;            // from equals, smallest anchors
#pragma unroll
        for (int k=0;k<NCH;k++){
            int a = tid + (k<<9);
            u32 v = sv[a];
            if (v > P){
                int p = atomicAdd(&sh_pos, 1);
                cs[p] = v; ca[p] = a;
            } else if (v == P && a < NA){
                int e = atomicAdd(&sh_ec, 1);
                if (e < 256) eqA[e] = (u32)a;
            }
        }
        __syncthreads();
        int ec = sh_ec;
        if (ec <= 256){
            for (int i = tid; i < 256; i += K2T) if (i >= ec) eqA[i] = 0xFFFFFFFFu;
            __syncthreads();
            for (int kk=2; kk<=256; kk<<=1){
                for (int j=kk>>1; j>0; j>>=1){
                    for (int i=tid; i<256; i+=K2T){
                        int ix = i ^ j;
                        if (ix > i){
                            u32 a0=eqA[i], a1=eqA[ix];
                            bool up = ((i & kk) == 0);
                            if ((a0 > a1) == up){ eqA[i]=a1; eqA[ix]=a0; }
                        }
                    }
                    __syncthreads();
                }
            }
            if (tid < krem){ cs[cg+tid] = P; ca[cg+tid] = (int)eqA[tid]; }
            __syncthreads();
        } else {
            // rare: binary search on anchor among equals
            int alo = 0, ahi = NA;        // cnt(a<alo)<krem, cnt(a<ahi)>=krem
            while (ahi - alo > 1){
                int amid = alo + ((ahi - alo) >> 1);
                u32 cc = 0;
#pragma unroll
                for (int k=0;k<NCH;k++){
                    int a = tid + (k<<9);
                    cc += (sv[a] == P && a < amid) ? 1u : 0u;
                }
                cc = __reduce_add_sync(0xffffffffu, cc);
                __syncthreads();
                if ((tid&31)==0) shw[tid>>5] = cc;
                __syncthreads();
                if (tid==0){ u32 t=0; for (int i=0;i<16;i++) t += shw[i]; shtot = t; }
                __syncthreads();
                if ((int)shtot >= krem) ahi = amid; else alo = amid;
            }
#pragma unroll
            for (int k=0;k<NCH;k++){
                int a = tid + (k<<9);
                if (sv[a] == P && a < ahi){
                    int p = atomicAdd(&sh_pos2, 1);
                    cs[cg+p] = P; ca[cg+p] = a;
                }
            }
            __syncthreads();
        }
    }

    // ---- sort 200 candidates desc by (score, anchor asc) via bitonic-256 ----
    for (int i = tid; i < 256; i += K2T){
        u64 nk = ~0ull;
        if (i < TOPK)
            nk = ~(((u64)cs[i] << 32) | (u64)(0xFFFFFFFFu - (u32)ca[i]));
        skeys[i] = nk;
    }
    __syncthreads();
    for (int kk=2; kk<=256; kk<<=1){
        for (int j=kk>>1; j>0; j>>=1){
            for (int i=tid; i<256; i+=K2T){
                int ix = i ^ j;
                if (ix > i){
                    u64 a0=skeys[i], a1=skeys[ix];
                    bool up = ((i & kk) == 0);
                    if ((a0 > a1) == up){ skeys[i]=a1; skeys[ix]=a0; }
                }
            }
            __syncthreads();
        }
    }
    if (tid < TOPK){
        u64 kk = ~skeys[tid];
        cs[tid] = (u32)(kk >> 32);
        ca[tid] = (int)(0xFFFFFFFFu - (u32)kk);
    }
    // valid prefix: scores > LOW_SCORE
    int m = __syncthreads_count(tid < TOPK && __uint_as_float(cs[tid]) > LOWSC);

    // ---- decode boxes for valid candidates + offset/area ----
    float off = 4.0f * (float)(c + 1);
    for (int i = tid; i < m; i += K2T){
        int a = ca[i];
        float4 d  = ((const float4*)deltas)[(size_t)b*NA + a];
        float4 db = ((const float4*)dboxg)[a];
        float w  = db.z - db.x, h = db.w - db.y;
        float cx = db.x + 0.5f*w, cy = db.y + 0.5f*h;
        float pcx = d.x/10.0f*w + cx;
        float pcy = d.y/10.0f*h + cy;
        float pw  = expf(d.z/5.0f)*w;
        float ph  = expf(d.w/5.0f)*h;
        float4 rb;
        rb.x = fminf(fmaxf(pcx - 0.5f*pw, 0.f), 1.f);
        rb.y = fminf(fmaxf(pcy - 0.5f*ph, 0.f), 1.f);
        rb.z = fminf(fmaxf(pcx + 0.5f*pw, 0.f), 1.f);
        rb.w = fminf(fmaxf(pcy + 0.5f*ph, 0.f), 1.f);
        rbox[i] = rb;
        float x0 = rb.x + off, y0 = rb.y + off;
        float x1 = rb.z + off, y1 = rb.w + off;
        sx0[i]=x0; sy0[i]=y0; sx1[i]=x1; sy1[i]=y1;
        sar[i] = (x1-x0)*(y1-y0);
    }
    for (int i = tid; i < TOPK*7; i += K2T) M[i] = 0u;
    __syncthreads();

    // ---- suppression matrix ----
    int nww = (m + 31) >> 5;
    int ntask = m * nww;
    int lane = tid & 31;
    for (int task = tid; task < ntask; task += K2T){
        int i = task / nww;
        int w = task - i*nww;
        float xi0=sx0[i], yi0=sy0[i], xi1=sx1[i], yi1=sy1[i], ai=sar[i];
        u32 bits = 0;
#pragma unroll
        for (int l=0;l<32;l++){
            int idx = (l + lane) & 31;
            int j = (w<<5) + idx;
            if (j < m && j > i){
                float xl = fmaxf(xi0, sx0[j]);
                float yt = fmaxf(yi0, sy0[j]);
                float xr = fminf(xi1, sx1[j]);
                float yb = fminf(yi1, sy1[j]);
                float inter = fmaxf(xr-xl, 0.f) * fmaxf(yb-yt, 0.f);
                float iou = inter / (ai + sar[j] - inter);
                if (iou > NMSTHR) bits |= (1u << idx);
            }
        }
        M[i*7 + w] = bits;
    }
    __syncthreads();

    // ---- serial greedy walk (thread 0, regs only) ----
    if (tid == 0){
        u32 r0=0,r1=0,r2=0,r3=0,r4=0,r5=0,r6=0;
#define NMSW(W, RW) { int lim = m - (W<<5); if (lim > 32) lim = 32; \
        for (int l=0;l<lim;l++){ \
            if (!((RW >> l) & 1u)){ const u32* row = &M[(((W)<<5)+l)*7]; \
                r0|=row[0]; r1|=row[1]; r2|=row[2]; r3|=row[3]; r4|=row[4]; r5|=row[5]; r6|=row[6]; } } }
        if (m >   0) NMSW(0, r0)
        if (m >  32) NMSW(1, r1)
        if (m >  64) NMSW(2, r2)
        if (m >  96) NMSW(3, r3)
        if (m > 128) NMSW(4, r4)
        if (m > 160) NMSW(5, r5)
        if (m > 192) NMSW(6, r6)
#undef NMSW
        skeep[0]=~r0; skeep[1]=~r1; skeep[2]=~r2; skeep[3]=~r3;
        skeep[4]=~r4; skeep[5]=~r5; skeep[6]=~r6;
    }
    __syncthreads();

    // ---- ordered compaction of kept -> global ----
    u32 bal = 0; bool kept = false;
    int w7 = tid >> 5;
    if (tid < 224){
        kept = (tid < m) && ((skeep[w7] >> lane) & 1u);
        bal = __ballot_sync(0xffffffffu, kept);
        if (lane == 0) warpcnt[w7] = __popc(bal);
    }
    __syncthreads();
    if (tid == 0){
        int s = 0;
        for (int w=0; w<7; w++){ warpbase[w] = s; s += warpcnt[w]; }
        sh_tot = s;
        g_kc[bc] = s;
    }
    __syncthreads();
    if (tid < 224 && kept){
        int pos = warpbase[w7] + __popc(bal & ((1u << lane) - 1u));
        g_ks[bc*TOPK + pos] = __uint_as_float(cs[tid]);
        g_ka[bc*TOPK + pos] = ca[tid];
        g_kb[bc*TOPK + pos] = rbox[tid];
    }
}

// ---------------- K3: per-batch rank-merge of 7 kept lists -------------------
__global__ __launch_bounds__(512) void k3_merge(float* __restrict__ out)
{
    __shared__ u64 sk[NFG*TOPK];
    __shared__ int scnt[NFG];

    int b = blockIdx.x;
    int tid = threadIdx.x;

    // zero output region
    for (int d = tid; d < DETS; d += 512){
        int base = b*DETS + d;
        out[base*4+0]=0.f; out[base*4+1]=0.f; out[base*4+2]=0.f; out[base*4+3]=0.f;
        out[NB*DETS*4 + base] = 0.f;
        out[NB*DETS*5 + base] = 0.f;
    }
    if (tid < NFG) scnt[tid] = g_kc[b*NFG + tid];
    __syncthreads();

    for (int idx = tid; idx < NFG*TOPK; idx += 512){
        int c = idx / TOPK;
        int p = idx - c*TOPK;
        u64 key = 0;
        if (p < scnt[c]){
            float s = g_ks[(b*NFG + c)*TOPK + p];
            int   a = g_ka[(b*NFG + c)*TOPK + p];
            key = ((u64)__float_as_uint(s) << 32)
                | ((u64)(u32)((7 - c) << 16))
                | (u64)(u32)(0xFFFF - a);
        }
        sk[idx] = key;
    }
    __syncthreads();

    for (int idx = tid; idx < NFG*TOPK; idx += 512){
        int c = idx / TOPK;
        int p = idx - c*TOPK;
        if (p < scnt[c]){
            u64 K = sk[idx];
            int r = p;
#pragma unroll
            for (int c2=0; c2<NFG; c2++){
                if (c2 == c) continue;
                const u64* L = sk + c2*TOPK;
                int blo = 0, bhi = scnt[c2];
                while (blo < bhi){
                    int mid = (blo + bhi) >> 1;
                    if (L[mid] > K) blo = mid + 1; else bhi = mid;
                }
                r += blo;
            }
            if (r < DETS){
                float4 bb = g_kb[(b*NFG + c)*TOPK + p];
                float  s  = __uint_as_float((u32)(K >> 32));
                int base = b*DETS + r;
                out[base*4+0]=bb.x; out[base*4+1]=bb.y;
                out[base*4+2]=bb.z; out[base*4+3]=bb.w;
                out[NB*DETS*4 + base] = s;
                out[NB*DETS*5 + base] = (float)(c + 1);
            }
        }
    }
}

// ---------------- launch ----------------------------------------------------
extern "C" void kernel_launch(void* const* d_in, const int* in_sizes, int n_in,
                              void* d_out, int out_size)
{
    const float* logits = (const float*)d_in[0];
    const float* deltas = (const float*)d_in[1];
    const float* dbox   = (const float*)d_in[2];
    float* out = (float*)d_out;

    static int smem_set = 0;
    if (!smem_set){
        cudaFuncSetAttribute(k2_select_nms, cudaFuncAttributeMaxDynamicSharedMemorySize,
                             NPAD*sizeof(u32));
        smem_set = 1;
    }

    int total = NB*NA;
    k1_softmax<<<(total + 255)/256, 256>>>(logits);
    k2_select_nms<<<NB*NFG, K2T, NPAD*sizeof(u32)>>>(deltas, dbox);
    k3_merge<<<NB, 512>>>(out);
}